// round 2
// baseline (speedup 1.0000x reference)
#include <cuda_runtime.h>
#include <cstdint>

// ---------------------------------------------------------------------------
// NodePredictor: y[b,n,:] = x[b,n,:] @ W[n] + b[n], out = y reshaped [B, N*DOUT]
// B=2048, N=64, DIN=DOUT=512, fp32.
//
// Target reality check: harness compiles PTX with .target sm_100 (no 'a'), so
// tcgen05/TMEM is unavailable. Use sm_80-era path: cp.async + ldmatrix +
// mma.sync.m16n8k8 tf32, CUTLASS-sm80 style, 3-stage pipeline.
//
// W is transposed + RNA-rounded to tf32 into __device__ scratch by a pre-pass
// so both A (x) and B (Wt) tiles are rows of 32 k-contiguous tf32 (128B =
// SW128 atom row) -> identical cp.async staging and conflict-free ldmatrix.
// x fragments are RNA-rounded in registers (removes tf32 truncation bias).
// ---------------------------------------------------------------------------

static constexpr int B_DIM   = 2048;
static constexpr int N_NODES = 64;
static constexpr int DIN     = 512;
static constexpr int DOUT    = 512;
static constexpr int OUT_W   = N_NODES * DOUT;   // 32768

static constexpr int TILE_M  = 128;
static constexpr int TILE_N  = 128;
static constexpr int TILE_K  = 32;               // 32 tf32 = 128 B row
static constexpr int K_ITERS = DIN / TILE_K;     // 16
static constexpr int THREADS = 256;
static constexpr int STAGES  = 3;

// SMEM: per stage A tile 128x128B = 16KB, B tile 16KB -> 32KB/stage
static constexpr int STAGE_BYTES = 32768;
static constexpr int SMEM_BIAS   = STAGES * STAGE_BYTES;          // 98304
static constexpr int SMEM_TOTAL  = SMEM_BIAS + TILE_N * 4;        // +512

// 64 MB scratch: Wt[n][dout][din], tf32(RNA)-rounded fp32 bits
__device__ float g_Wt[(size_t)N_NODES * DOUT * DIN];

// ---------------------------------------------------------------------------
__device__ __forceinline__ uint32_t smem_u32(const void* p) {
    uint32_t a;
    asm("{ .reg .u64 t; cvta.to.shared.u64 t, %1; cvt.u32.u64 %0, t; }" : "=r"(a) : "l"(p));
    return a;
}
__device__ __forceinline__ uint32_t rna_tf32(float x) {
    uint32_t r;
    asm("cvt.rna.tf32.f32 %0, %1;" : "=r"(r) : "f"(x));
    return r;
}
__device__ __forceinline__ uint32_t sw128(uint32_t off) {
    return off ^ ((off >> 3) & 0x70u);
}
__device__ __forceinline__ void cp_async16(uint32_t smem_dst, const void* gmem_src) {
    asm volatile("cp.async.cg.shared.global [%0], [%1], 16;"
                 :: "r"(smem_dst), "l"(gmem_src) : "memory");
}
__device__ __forceinline__ void cp_commit() {
    asm volatile("cp.async.commit_group;" ::: "memory");
}
template <int N>
__device__ __forceinline__ void cp_wait() {
    asm volatile("cp.async.wait_group %0;" :: "n"(N) : "memory");
}
__device__ __forceinline__ void ldsm_x4(uint32_t* r, uint32_t addr) {
    asm volatile("ldmatrix.sync.aligned.m8n8.x4.shared.b16 {%0,%1,%2,%3}, [%4];"
                 : "=r"(r[0]), "=r"(r[1]), "=r"(r[2]), "=r"(r[3]) : "r"(addr));
}
__device__ __forceinline__ void mma_tf32(float* c, const uint32_t* a, uint32_t b0, uint32_t b1) {
    asm volatile(
        "mma.sync.aligned.m16n8k8.row.col.f32.tf32.tf32.f32 "
        "{%0,%1,%2,%3}, {%4,%5,%6,%7}, {%8,%9}, {%0,%1,%2,%3};"
        : "+f"(c[0]), "+f"(c[1]), "+f"(c[2]), "+f"(c[3])
        : "r"(a[0]), "r"(a[1]), "r"(a[2]), "r"(a[3]), "r"(b0), "r"(b1));
}

// ---------------------------------------------------------------------------
// Pre-pass: Wt[n][o][i] = rna_tf32(W[n][i][o])
// ---------------------------------------------------------------------------
__global__ void wt_transpose_kernel(const float* __restrict__ W) {
    __shared__ float tile[32][33];
    const int n  = blockIdx.z;
    const int i0 = blockIdx.x * 32;   // din
    const int o0 = blockIdx.y * 32;   // dout
    const int tx = threadIdx.x, ty = threadIdx.y;   // 32 x 8

    const float* src = W + ((size_t)n * DIN + i0) * DOUT + o0;
#pragma unroll
    for (int r = 0; r < 32; r += 8)
        tile[ty + r][tx] = src[(size_t)(ty + r) * DOUT + tx];
    __syncthreads();

    float* dst = g_Wt + ((size_t)n * DOUT + o0) * DIN + i0;
#pragma unroll
    for (int r = 0; r < 32; r += 8)
        dst[(size_t)(ty + r) * DIN + tx] = __uint_as_float(rna_tf32(tile[tx][ty + r]));
}

// ---------------------------------------------------------------------------
// Main GEMM: CTA = [128M x 128N] tile of one node. 8 warps, warptile 64x32.
// ---------------------------------------------------------------------------
__global__ __launch_bounds__(THREADS, 2)
void node_gemm_kernel(const float* __restrict__ x, const float* __restrict__ bias,
                      float* __restrict__ out) {
    extern __shared__ char smem[];
    const uint32_t sbase = smem_u32(smem);
    const int tid  = threadIdx.x;
    const int wid  = tid >> 5;
    const int lane = tid & 31;

    // block decode: nt fastest (L2 reuse of A slab), then mt, then node
    const int bx = blockIdx.x;
    const int n  = bx >> 6;
    const int mt = (bx >> 2) & 15;
    const int nt = bx & 3;
    const int m_base = mt * TILE_M;
    const int o_base = nt * TILE_N;

    // bias -> smem
    if (tid < TILE_N)
        reinterpret_cast<float*>(smem + SMEM_BIAS)[tid] = bias[n * DOUT + o_base + tid];

    // ---- cp.async staging setup: thread t stages row t/2, chunks (t&1)*4..+3
    const int st_row = tid >> 1;
    const int st_cb  = (tid & 1) * 4;               // chunk base (16B units)
    const float* a_src = x + ((size_t)(m_base + st_row) * N_NODES + n) * DIN + st_cb * 4;
    const float* b_src = g_Wt + ((size_t)(n * DOUT + o_base + st_row)) * DIN + st_cb * 4;
    uint32_t st_dst[4];
#pragma unroll
    for (int j = 0; j < 4; ++j)
        st_dst[j] = sw128((uint32_t)st_row * 128u + (uint32_t)(st_cb + j) * 16u);

    auto issue = [&](int stage, int kc) {
        const uint32_t as = sbase + stage * STAGE_BYTES;
        const uint32_t bs = as + 16384;
        const float* ap = a_src + kc * TILE_K;
        const float* bp = b_src + kc * TILE_K;
#pragma unroll
        for (int j = 0; j < 4; ++j) cp_async16(as + st_dst[j], ap + j * 4);
#pragma unroll
        for (int j = 0; j < 4; ++j) cp_async16(bs + st_dst[j], bp + j * 4);
        cp_commit();
    };

    // ---- ldmatrix lane address components
    const int wm = wid >> 2;       // 0..1  (M)
    const int wn = wid & 3;        // 0..3  (N)
    // A: matrices (r0-7,k0-3),(r8-15,k0-3),(r0-7,k4-7),(r8-15,k4-7)
    const uint32_t a_row  = (uint32_t)(wm * 64 + (lane & 15));
    const uint32_t a_cadd = (uint32_t)(lane >> 4);       // +1 chunk for k4-7
    // B: matrices (n0-7,k0-3),(n0-7,k4-7),(n8-15,k0-3),(n8-15,k4-7)
    const uint32_t b_row  = (uint32_t)(wn * 32 + ((lane >> 4) << 3) + (lane & 7));
    const uint32_t b_cadd = (uint32_t)((lane >> 3) & 1);

    float c[4][4][4];
#pragma unroll
    for (int i = 0; i < 4; ++i)
#pragma unroll
        for (int j = 0; j < 4; ++j)
#pragma unroll
            for (int k = 0; k < 4; ++k) c[i][j][k] = 0.0f;

    auto compute = [&](int stage) {
        const uint32_t as = sbase + stage * STAGE_BYTES;
        const uint32_t bs = as + 16384;
#pragma unroll
        for (int ks = 0; ks < 4; ++ks) {
            const uint32_t ac = 2 * ks + a_cadd;
            const uint32_t bc = 2 * ks + b_cadd;
            uint32_t a[4][4];
#pragma unroll
            for (int m = 0; m < 4; ++m) {
                ldsm_x4(a[m], as + sw128((a_row + m * 16) * 128u + ac * 16u));
#pragma unroll
                for (int r = 0; r < 4; ++r)
                    a[m][r] = rna_tf32(__uint_as_float(a[m][r]));
            }
            uint32_t bq[8];   // {nt0 b0,b1, nt1 b0,b1, nt2 b0,b1, nt3 b0,b1}
            ldsm_x4(bq + 0, bs + sw128((b_row +  0) * 128u + bc * 16u));
            ldsm_x4(bq + 4, bs + sw128((b_row + 16) * 128u + bc * 16u));
#pragma unroll
            for (int m = 0; m < 4; ++m)
#pragma unroll
                for (int q = 0; q < 4; ++q)
                    mma_tf32(c[m][q], a[m], bq[2 * q], bq[2 * q + 1]);
        }
    };

    // ---- pipeline: prologue fills 2 stages
    issue(0, 0);
    issue(1, 1);
    cp_wait<1>();
    __syncthreads();

    for (int kc = 0; kc < K_ITERS; ++kc) {
        const int s = kc % STAGES;
        if (kc + 2 < K_ITERS) issue((kc + 2) % STAGES, kc + 2);
        compute(s);
        if (kc + 1 < K_ITERS) {
            if (kc + 2 < K_ITERS) cp_wait<1>(); else cp_wait<0>();
            __syncthreads();
        }
    }

    // ---- epilogue: add bias, store (c0,c1) / (c2,c3) as float2
    const float* bsm = reinterpret_cast<const float*>(smem + SMEM_BIAS);
    const int r_top = m_base + wm * 64 + (lane >> 2);
    const int lc0   = wn * 32 + (lane & 3) * 2;
#pragma unroll
    for (int m = 0; m < 4; ++m) {
#pragma unroll
        for (int q = 0; q < 4; ++q) {
            const int lc = lc0 + q * 8;
            const float b0 = bsm[lc], b1 = bsm[lc + 1];
            float* d0 = out + (size_t)(r_top + m * 16) * OUT_W + n * DOUT + o_base + lc;
            float* d1 = d0 + 8 * OUT_W;
            float2 v0 = { c[m][q][0] + b0, c[m][q][1] + b1 };
            float2 v1 = { c[m][q][2] + b0, c[m][q][3] + b1 };
            *reinterpret_cast<float2*>(d0) = v0;
            *reinterpret_cast<float2*>(d1) = v1;
        }
    }
}

// ---------------------------------------------------------------------------
extern "C" void kernel_launch(void* const* d_in, const int* in_sizes, int n_in,
                              void* d_out, int out_size) {
    const float* x = (const float*)d_in[0];
    const float* W = (const float*)d_in[1];
    const float* b = (const float*)d_in[2];
    float* out = (float*)d_out;

    cudaFuncSetAttribute(node_gemm_kernel,
                         cudaFuncAttributeMaxDynamicSharedMemorySize, SMEM_TOTAL);

    wt_transpose_kernel<<<dim3(DIN / 32, DOUT / 32, N_NODES), dim3(32, 8)>>>(W);

    const int grid = N_NODES * (B_DIM / TILE_M) * (DOUT / TILE_N);  // 64*16*4 = 4096
    node_gemm_kernel<<<grid, THREADS, SMEM_TOTAL>>>(x, b, out);
}